// round 1
// baseline (speedup 1.0000x reference)
#include <cuda_runtime.h>
#include <cuda_bf16.h>
#include <mma.h>
#include <math.h>

using namespace nvcuda;

#define B_SZ   2048
#define C_SZ   512
#define N_SZ   256
#define F_SZ   256
#define K_TOP  4
#define LOG_F  5.545177444479562f

// ---------------- scratch (static device memory; no allocation) ----------------
__device__ __align__(16) __nv_bfloat16 g_xn  [B_SZ * C_SZ];
__device__ __align__(16) __nv_bfloat16 g_h1  [B_SZ * C_SZ];
__device__ __align__(16) __nv_bfloat16 g_h2  [B_SZ * C_SZ];
__device__ __align__(16) float         g_coarse[B_SZ * N_SZ];
__device__ __align__(16) int           g_topidx[B_SZ * K_TOP];
__device__ __align__(16) __nv_bfloat16 g_fin [B_SZ * K_TOP * 2 * C_SZ];
__device__ __align__(16) __nv_bfloat16 g_g1  [B_SZ * K_TOP * C_SZ];
__device__ __align__(16) __nv_bfloat16 g_g2  [B_SZ * K_TOP * C_SZ];
__device__ __align__(16) float         g_fine[B_SZ * K_TOP * F_SZ];
__device__ __align__(16) __nv_bfloat16 g_wbf [1572864];   // all weights in bf16

// weight offsets in g_wbf
#define W_CW1 0
#define W_CW2 262144
#define W_CW3 524288
#define W_FW1 655360
#define W_FW2 1179648
#define W_FW3 1441792

// ---------------- helpers ----------------
__device__ __forceinline__ float warp_sum(float v) {
    #pragma unroll
    for (int o = 16; o; o >>= 1) v += __shfl_xor_sync(0xffffffffu, v, o);
    return v;
}
__device__ __forceinline__ float warp_max(float v) {
    #pragma unroll
    for (int o = 16; o; o >>= 1) v = fmaxf(v, __shfl_xor_sync(0xffffffffu, v, o));
    return v;
}
__device__ __forceinline__ float gelu_tanh(float x) {
    float x3 = x * x * x;
    return 0.5f * x * (1.0f + tanhf(0.7978845608028654f * (x + 0.044715f * x3)));
}

// ---------------- fp32 -> bf16 conversion ----------------
__global__ void cvt_kernel(const float* __restrict__ s, __nv_bfloat16* __restrict__ d, int n) {
    int i = (blockIdx.x * blockDim.x + threadIdx.x) * 4;
    if (i < n) {
        float4 v = *(const float4*)(s + i);
        __nv_bfloat162 p0 = __floats2bfloat162_rn(v.x, v.y);
        __nv_bfloat162 p1 = __floats2bfloat162_rn(v.z, v.w);
        ((__nv_bfloat162*)(d + i))[0] = p0;
        ((__nv_bfloat162*)(d + i))[1] = p1;
    }
}

// ---------------- LayerNorm(x) + no_op head ----------------
// 128 threads per row; writes xn (bf16) and out[b * 65537] = xn @ nop_w + nop_b
__global__ void ln_noop_kernel(const float* __restrict__ x,
                               const float* __restrict__ g, const float* __restrict__ b,
                               const float* __restrict__ nw, const float* __restrict__ nb,
                               __nv_bfloat16* __restrict__ xn, float* __restrict__ out) {
    int row = blockIdx.x, t = threadIdx.x;
    int w = t >> 5, lane = t & 31;
    float4 v = ((const float4*)(x + (size_t)row * C_SZ))[t];

    float s  = v.x + v.y + v.z + v.w;
    float sq = v.x * v.x + v.y * v.y + v.z * v.z + v.w * v.w;

    __shared__ float rs[4], rq[4], rn[4];
    float ws = warp_sum(s), wq = warp_sum(sq);
    if (lane == 0) { rs[w] = ws; rq[w] = wq; }
    __syncthreads();
    float tot_s = rs[0] + rs[1] + rs[2] + rs[3];
    float tot_q = rq[0] + rq[1] + rq[2] + rq[3];
    float mean = tot_s * (1.0f / C_SZ);
    float var  = tot_q * (1.0f / C_SZ) - mean * mean;
    float rstd = rsqrtf(var + 1e-5f);

    float4 gg = ((const float4*)g)[t];
    float4 bb = ((const float4*)b)[t];
    float y0 = (v.x - mean) * rstd * gg.x + bb.x;
    float y1 = (v.y - mean) * rstd * gg.y + bb.y;
    float y2 = (v.z - mean) * rstd * gg.z + bb.z;
    float y3 = (v.w - mean) * rstd * gg.w + bb.w;

    __nv_bfloat162 p0 = __floats2bfloat162_rn(y0, y1);
    __nv_bfloat162 p1 = __floats2bfloat162_rn(y2, y3);
    __nv_bfloat16* xr = xn + (size_t)row * C_SZ + t * 4;
    ((__nv_bfloat162*)xr)[0] = p0;
    ((__nv_bfloat162*)xr)[1] = p1;

    float4 ww = ((const float4*)nw)[t];
    float acc = y0 * ww.x + y1 * ww.y + y2 * ww.z + y3 * ww.w;
    float wacc = warp_sum(acc);
    if (lane == 0) rn[w] = wacc;
    __syncthreads();
    if (t == 0) out[(size_t)row * 65537] = rn[0] + rn[1] + rn[2] + rn[3] + nb[0];
}

// ---------------- WMMA bf16 GEMM: C = act(A @ B + bias) ----------------
// A: MxK row-major bf16, B: KxN row-major bf16, bias: N fp32
// block tile 128x128, k-tile 32, 8 warps (2x4), warp tile 64x32, double buffered smem
#define GBM 128
#define GBN 128
#define GBK 32
#define GLDA 48     // 32+16, 96B rows (16B multiple)
#define GLDB 136    // 128+8, 272B rows (16B multiple)

template<typename OutT, bool GELU>
__global__ void __launch_bounds__(256) gemm_bias_act(
    const __nv_bfloat16* __restrict__ A, const __nv_bfloat16* __restrict__ Bw,
    const float* __restrict__ bias, OutT* __restrict__ Cout,
    int M, int N, int K) {

    __shared__ __align__(32) unsigned char smem_raw[41984];
    __nv_bfloat16* As = (__nv_bfloat16*)smem_raw;                   // [2][128][48]
    __nv_bfloat16* Bs = As + 2 * GBM * GLDA;                        // [2][32][136]
    float* epi = (float*)smem_raw;                                  // reused for epilogue

    int tid = threadIdx.x;
    int warp = tid >> 5, lane = tid & 31;
    int wm = warp >> 2, wn = warp & 3;       // 2 x 4 warp grid
    int bm = blockIdx.y, bn = blockIdx.x;

    wmma::fragment<wmma::accumulator, 16, 16, 16, float> acc[4][2];
    #pragma unroll
    for (int i = 0; i < 4; i++)
        #pragma unroll
        for (int j = 0; j < 2; j++)
            wmma::fill_fragment(acc[i][j], 0.0f);

    const int KT = K / GBK;

    // initial tile -> buffer 0
    {
        #pragma unroll
        for (int i = 0; i < 2; i++) {
            int idx = tid + i * 256;
            int row = idx >> 2, kv = (idx & 3) * 8;
            uint4 v = *(const uint4*)(A + (size_t)(bm * GBM + row) * K + kv);
            *(uint4*)(As + row * GLDA + kv) = v;
        }
        #pragma unroll
        for (int i = 0; i < 2; i++) {
            int idx = tid + i * 256;
            int row = idx >> 4, cv = (idx & 15) * 8;
            uint4 v = *(const uint4*)(Bw + (size_t)row * N + bn * GBN + cv);
            *(uint4*)(Bs + row * GLDB + cv) = v;
        }
    }
    __syncthreads();

    for (int kt = 0; kt < KT; kt++) {
        uint4 ra[2], rb[2];
        bool pre = (kt + 1 < KT);
        if (pre) {
            int k0 = (kt + 1) * GBK;
            #pragma unroll
            for (int i = 0; i < 2; i++) {
                int idx = tid + i * 256;
                int row = idx >> 2, kv = (idx & 3) * 8;
                ra[i] = *(const uint4*)(A + (size_t)(bm * GBM + row) * K + k0 + kv);
            }
            #pragma unroll
            for (int i = 0; i < 2; i++) {
                int idx = tid + i * 256;
                int row = idx >> 4, cv = (idx & 15) * 8;
                rb[i] = *(const uint4*)(Bw + (size_t)(k0 + row) * N + bn * GBN + cv);
            }
        }
        const __nv_bfloat16* Ab = As + (kt & 1) * GBM * GLDA;
        const __nv_bfloat16* Bb = Bs + (kt & 1) * GBK * GLDB;
        #pragma unroll
        for (int ks = 0; ks < GBK; ks += 16) {
            wmma::fragment<wmma::matrix_a, 16, 16, 16, __nv_bfloat16, wmma::row_major> af[4];
            wmma::fragment<wmma::matrix_b, 16, 16, 16, __nv_bfloat16, wmma::row_major> bf[2];
            #pragma unroll
            for (int i = 0; i < 4; i++)
                wmma::load_matrix_sync(af[i], Ab + (size_t)(wm * 64 + i * 16) * GLDA + ks, GLDA);
            #pragma unroll
            for (int j = 0; j < 2; j++)
                wmma::load_matrix_sync(bf[j], Bb + (size_t)ks * GLDB + wn * 32 + j * 16, GLDB);
            #pragma unroll
            for (int i = 0; i < 4; i++)
                #pragma unroll
                for (int j = 0; j < 2; j++)
                    wmma::mma_sync(acc[i][j], af[i], bf[j], acc[i][j]);
        }
        if (pre) {
            int s = (kt + 1) & 1;
            #pragma unroll
            for (int i = 0; i < 2; i++) {
                int idx = tid + i * 256;
                int row = idx >> 2, kv = (idx & 3) * 8;
                *(uint4*)(As + s * GBM * GLDA + row * GLDA + kv) = ra[i];
            }
            #pragma unroll
            for (int i = 0; i < 2; i++) {
                int idx = tid + i * 256;
                int row = idx >> 4, cv = (idx & 15) * 8;
                *(uint4*)(Bs + s * GBK * GLDB + row * GLDB + cv) = rb[i];
            }
            __syncthreads();
        }
    }
    __syncthreads();   // before smem reuse for epilogue

    float* ep = epi + warp * 16 * 20;   // per-warp 16x20 staging
    #pragma unroll
    for (int i = 0; i < 4; i++) {
        #pragma unroll
        for (int j = 0; j < 2; j++) {
            wmma::store_matrix_sync(ep, acc[i][j], 20, wmma::mem_row_major);
            __syncwarp();
            int grow0 = bm * GBM + wm * 64 + i * 16;
            int gcol0 = bn * GBN + wn * 32 + j * 16;
            #pragma unroll
            for (int e = lane; e < 256; e += 32) {
                int r = e >> 4, c = e & 15;
                float v = ep[r * 20 + c] + bias[gcol0 + c];
                if (GELU) v = gelu_tanh(v);
                if (sizeof(OutT) == 2)
                    ((__nv_bfloat16*)Cout)[(size_t)(grow0 + r) * N + gcol0 + c] = __float2bfloat16(v);
                else
                    ((float*)Cout)[(size_t)(grow0 + r) * N + gcol0 + c] = v;
            }
            __syncwarp();
        }
    }
}

// ---------------- top-4 per row (one warp per row) ----------------
__global__ void topk_kernel(const float* __restrict__ coarse, int* __restrict__ idx) {
    int warp = threadIdx.x >> 5, lane = threadIdx.x & 31;
    int row = blockIdx.x * 8 + warp;
    const float* cr = coarse + (size_t)row * N_SZ;
    float4 a = ((const float4*)cr)[lane * 2];
    float4 b = ((const float4*)cr)[lane * 2 + 1];
    float v[8] = {a.x, a.y, a.z, a.w, b.x, b.y, b.z, b.w};
    int base = lane * 8;
    #pragma unroll
    for (int k = 0; k < K_TOP; k++) {
        float bv = v[0]; int bi = 0;
        #pragma unroll
        for (int j = 1; j < 8; j++) if (v[j] > bv) { bv = v[j]; bi = j; }
        int bcol = base + bi;
        #pragma unroll
        for (int o = 16; o; o >>= 1) {
            float ov = __shfl_down_sync(0xffffffffu, bv, o);
            int   oc = __shfl_down_sync(0xffffffffu, bcol, o);
            if (ov > bv || (ov == bv && oc < bcol)) { bv = ov; bcol = oc; }
        }
        bcol = __shfl_sync(0xffffffffu, bcol, 0);
        if (lane == 0) idx[row * K_TOP + k] = bcol;
        if (bcol >= base && bcol < base + 8) v[bcol - base] = -INFINITY;
    }
}

// ---------------- gather emb[idx], LN, concat with xn -> fin ----------------
__global__ void embcat_kernel(const int* __restrict__ idx, const float* __restrict__ emb,
                              const float* __restrict__ g, const float* __restrict__ b,
                              const __nv_bfloat16* __restrict__ xn,
                              __nv_bfloat16* __restrict__ fin) {
    int r = blockIdx.x, t = threadIdx.x;         // 128 threads
    int w = t >> 5, lane = t & 31;
    int bq = r >> 2;
    int n = idx[r];

    // first half: copy xn (bf16)
    uint2 xv = ((const uint2*)(xn + (size_t)bq * C_SZ))[t];
    ((uint2*)(fin + (size_t)r * 2 * C_SZ))[t] = xv;

    // second half: LN(emb[n])
    float4 v = ((const float4*)(emb + (size_t)n * C_SZ))[t];
    float s  = v.x + v.y + v.z + v.w;
    float sq = v.x * v.x + v.y * v.y + v.z * v.z + v.w * v.w;
    __shared__ float rs[4], rq[4];
    float ws = warp_sum(s), wq = warp_sum(sq);
    if (lane == 0) { rs[w] = ws; rq[w] = wq; }
    __syncthreads();
    float tot_s = rs[0] + rs[1] + rs[2] + rs[3];
    float tot_q = rq[0] + rq[1] + rq[2] + rq[3];
    float mean = tot_s * (1.0f / C_SZ);
    float var  = tot_q * (1.0f / C_SZ) - mean * mean;
    float rstd = rsqrtf(var + 1e-5f);

    float4 gg = ((const float4*)g)[t];
    float4 bb = ((const float4*)b)[t];
    float y0 = (v.x - mean) * rstd * gg.x + bb.x;
    float y1 = (v.y - mean) * rstd * gg.y + bb.y;
    float y2 = (v.z - mean) * rstd * gg.z + bb.z;
    float y3 = (v.w - mean) * rstd * gg.w + bb.w;
    __nv_bfloat162 p0 = __floats2bfloat162_rn(y0, y1);
    __nv_bfloat162 p1 = __floats2bfloat162_rn(y2, y3);
    __nv_bfloat16* fr = fin + (size_t)r * 2 * C_SZ + C_SZ + t * 4;
    ((__nv_bfloat162*)fr)[0] = p0;
    ((__nv_bfloat162*)fr)[1] = p1;
}

// ---------------- vals = coarse[b, idx] + log_softmax(fine), in place ----------------
__global__ void vals_kernel(float* __restrict__ fine, const float* __restrict__ coarse,
                            const int* __restrict__ idx) {
    int warp = threadIdx.x >> 5, lane = threadIdx.x & 31;
    int r = blockIdx.x * 8 + warp;
    float4* fr = (float4*)(fine + (size_t)r * F_SZ);
    float4 a = fr[lane * 2], b = fr[lane * 2 + 1];
    float v[8] = {a.x, a.y, a.z, a.w, b.x, b.y, b.z, b.w};
    float m = v[0];
    #pragma unroll
    for (int j = 1; j < 8; j++) m = fmaxf(m, v[j]);
    m = warp_max(m);
    float s = 0.0f;
    #pragma unroll
    for (int j = 0; j < 8; j++) s += expf(v[j] - m);
    s = warp_sum(s);
    float add = coarse[(size_t)(r >> 2) * N_SZ + idx[r]] - m - logf(s);
    a.x = v[0] + add; a.y = v[1] + add; a.z = v[2] + add; a.w = v[3] + add;
    b.x = v[4] + add; b.y = v[5] + add; b.z = v[6] + add; b.w = v[7] + add;
    fr[lane * 2] = a; fr[lane * 2 + 1] = b;
}

// ---------------- permuted broadcast fill of the (B, N*F) output ----------------
// block = (ch0, b); writes the contiguous 4096-float span
// out pos within span: p = fh0*256 + ch1*16 + fh1; value = dense[b, ch0*16+ch1, fh0*16+fh1]
__global__ void fill_kernel(const float* __restrict__ coarse, const float* __restrict__ vals,
                            const int* __restrict__ idx, float* __restrict__ out) {
    int ch0 = blockIdx.x, b = blockIdx.y, t = threadIdx.x;   // 256 threads
    __shared__ float base[16];
    __shared__ int ov[16];
    if (t < 16) { base[t] = coarse[(size_t)b * N_SZ + ch0 * 16 + t] - LOG_F; ov[t] = -1; }
    __syncthreads();
    if (t < K_TOP) { int n = idx[b * K_TOP + t]; if ((n >> 4) == ch0) ov[n & 15] = t; }
    __syncthreads();

    size_t obase = (size_t)b * 65537 + 1 + (size_t)ch0 * 4096;
    int head = (int)((4 - (obase & 3)) & 3);
    int nvec = (4096 - head) >> 2;
    int tail = 4096 - head - nvec * 4;

    for (int i = t; i < nvec; i += 256) {
        int p0 = head + i * 4;
        float4 w;
        float* wp = &w.x;
        #pragma unroll
        for (int u = 0; u < 4; u++) {
            int p = p0 + u;
            int ch1 = (p >> 4) & 15;
            int k = ov[ch1];
            wp[u] = (k < 0) ? base[ch1]
                            : vals[((size_t)b * K_TOP + k) * F_SZ + ((p >> 8) << 4) + (p & 15)];
        }
        *(float4*)(out + obase + p0) = w;
    }
    // scalar head/tail
    int p = -1;
    if (t < head) p = t;
    else if (t - head < tail) p = head + nvec * 4 + (t - head);
    if (p >= 0) {
        int ch1 = (p >> 4) & 15;
        int k = ov[ch1];
        float v = (k < 0) ? base[ch1]
                          : vals[((size_t)b * K_TOP + k) * F_SZ + ((p >> 8) << 4) + (p & 15)];
        out[obase + p] = v;
    }
}

// ---------------- launch ----------------
extern "C" void kernel_launch(void* const* d_in, const int* in_sizes, int n_in,
                              void* d_out, int out_size) {
    const float* x     = (const float*)d_in[0];
    const float* in_g  = (const float*)d_in[1];
    const float* in_b  = (const float*)d_in[2];
    const float* nop_w = (const float*)d_in[3];
    const float* nop_b = (const float*)d_in[4];
    const float* c_w1  = (const float*)d_in[5];
    const float* c_b1  = (const float*)d_in[6];
    const float* c_w2  = (const float*)d_in[7];
    const float* c_b2  = (const float*)d_in[8];
    const float* c_w3  = (const float*)d_in[9];
    const float* c_b3  = (const float*)d_in[10];
    const float* emb   = (const float*)d_in[11];
    const float* emb_g = (const float*)d_in[12];
    const float* emb_b = (const float*)d_in[13];
    const float* f_w1  = (const float*)d_in[14];
    const float* f_b1  = (const float*)d_in[15];
    const float* f_w2  = (const float*)d_in[16];
    const float* f_b2  = (const float*)d_in[17];
    const float* f_w3  = (const float*)d_in[18];
    const float* f_b3  = (const float*)d_in[19];
    float* out = (float*)d_out;

    __nv_bfloat16 *xn, *h1, *h2, *fin, *g1, *g2, *wbf;
    float *coarse, *fine;
    int *idx;
    cudaGetSymbolAddress((void**)&xn,     g_xn);
    cudaGetSymbolAddress((void**)&h1,     g_h1);
    cudaGetSymbolAddress((void**)&h2,     g_h2);
    cudaGetSymbolAddress((void**)&coarse, g_coarse);
    cudaGetSymbolAddress((void**)&idx,    g_topidx);
    cudaGetSymbolAddress((void**)&fin,    g_fin);
    cudaGetSymbolAddress((void**)&g1,     g_g1);
    cudaGetSymbolAddress((void**)&g2,     g_g2);
    cudaGetSymbolAddress((void**)&fine,   g_fine);
    cudaGetSymbolAddress((void**)&wbf,    g_wbf);

    // weight conversion fp32 -> bf16
    cvt_kernel<<<262144 / 1024, 256>>>(c_w1, wbf + W_CW1, 262144);
    cvt_kernel<<<262144 / 1024, 256>>>(c_w2, wbf + W_CW2, 262144);
    cvt_kernel<<<131072 / 1024, 256>>>(c_w3, wbf + W_CW3, 131072);
    cvt_kernel<<<524288 / 1024, 256>>>(f_w1, wbf + W_FW1, 524288);
    cvt_kernel<<<262144 / 1024, 256>>>(f_w2, wbf + W_FW2, 262144);
    cvt_kernel<<<131072 / 1024, 256>>>(f_w3, wbf + W_FW3, 131072);

    // LN + no_op head
    ln_noop_kernel<<<B_SZ, 128>>>(x, in_g, in_b, nop_w, nop_b, xn, out);

    // coarse MLP
    gemm_bias_act<__nv_bfloat16, true ><<<dim3(4, 16), 256>>>(xn, wbf + W_CW1, c_b1, h1, 2048, 512, 512);
    gemm_bias_act<__nv_bfloat16, true ><<<dim3(4, 16), 256>>>(h1, wbf + W_CW2, c_b2, h2, 2048, 512, 512);
    gemm_bias_act<float,         false><<<dim3(2, 16), 256>>>(h2, wbf + W_CW3, c_b3, coarse, 2048, 256, 512);

    // top-4 + gather/LN/concat
    topk_kernel<<<B_SZ / 8, 256>>>(coarse, idx);
    embcat_kernel<<<B_SZ * K_TOP, 128>>>(idx, emb, emb_g, emb_b, xn, fin);

    // fine MLP
    gemm_bias_act<__nv_bfloat16, true ><<<dim3(4, 64), 256>>>(fin, wbf + W_FW1, f_b1, g1, 8192, 512, 1024);
    gemm_bias_act<__nv_bfloat16, true ><<<dim3(4, 64), 256>>>(g1,  wbf + W_FW2, f_b2, g2, 8192, 512, 512);
    gemm_bias_act<float,         false><<<dim3(2, 64), 256>>>(g2,  wbf + W_FW3, f_b3, fine, 8192, 256, 512);

    // log-softmax + scatter values, then the big permuted broadcast fill
    vals_kernel<<<B_SZ * K_TOP / 8, 256>>>(fine, coarse, idx);
    fill_kernel<<<dim3(16, B_SZ), 256>>>(coarse, fine, idx, out);
}

// round 3
// speedup vs baseline: 1.3704x; 1.3704x over previous
#include <cuda_runtime.h>
#include <cuda_bf16.h>
#include <math.h>
#include <stdint.h>

#define B_SZ   2048
#define C_SZ   512
#define N_SZ   256
#define F_SZ   256
#define K_TOP  4
#define LOG_F  5.545177444479562f

// ---------------- scratch (static device memory; no allocation) ----------------
__device__ __align__(16) __nv_bfloat16 g_xn  [B_SZ * C_SZ];
__device__ __align__(16) __nv_bfloat16 g_h1  [B_SZ * C_SZ];
__device__ __align__(16) __nv_bfloat16 g_h2  [B_SZ * C_SZ];
__device__ __align__(16) float         g_coarse[B_SZ * N_SZ];
__device__ __align__(16) int           g_topidx[B_SZ * K_TOP];
__device__ __align__(16) __nv_bfloat16 g_fin [B_SZ * K_TOP * 2 * C_SZ];
__device__ __align__(16) __nv_bfloat16 g_g1  [B_SZ * K_TOP * C_SZ];
__device__ __align__(16) __nv_bfloat16 g_g2  [B_SZ * K_TOP * C_SZ];
__device__ __align__(16) float         g_fine[B_SZ * K_TOP * F_SZ];
__device__ __align__(16) __nv_bfloat16 g_wbf [1572864];   // all weights, transposed, bf16

// weight offsets in g_wbf (all stored [N][K] row-major = W^T)
#define W_CW1 0
#define W_CW2 262144
#define W_CW3 524288
#define W_FW1 655360
#define W_FW2 1179648
#define W_FW3 1441792

// ---------------- PTX helpers ----------------
__device__ __forceinline__ uint32_t smem_to_u32(const void* p) {
    uint32_t a;
    asm("{ .reg .u64 t; cvta.to.shared.u64 t, %1; cvt.u32.u64 %0, t; }" : "=r"(a) : "l"(p));
    return a;
}
#define CP16(dst, src)    asm volatile("cp.async.cg.shared.global [%0], [%1], 16;" :: "r"(dst), "l"(src))
#define CP_COMMIT()       asm volatile("cp.async.commit_group;" ::: "memory")
#define CP_WAIT(n)        asm volatile("cp.async.wait_group %0;" :: "n"(n) : "memory")

#define LDSM4(r, addr)                                                           \
    asm volatile("ldmatrix.sync.aligned.m8n8.x4.shared.b16 {%0,%1,%2,%3}, [%4];" \
        : "=r"((r)[0]), "=r"((r)[1]), "=r"((r)[2]), "=r"((r)[3]) : "r"(addr))

__device__ __forceinline__ void mma16816(float* d, const uint32_t* a,
                                         uint32_t b0, uint32_t b1) {
    asm volatile("mma.sync.aligned.m16n8k16.row.col.f32.bf16.bf16.f32 "
        "{%0,%1,%2,%3}, {%4,%5,%6,%7}, {%8,%9}, {%0,%1,%2,%3};"
        : "+f"(d[0]), "+f"(d[1]), "+f"(d[2]), "+f"(d[3])
        : "r"(a[0]), "r"(a[1]), "r"(a[2]), "r"(a[3]), "r"(b0), "r"(b1));
}

// ---------------- misc helpers ----------------
__device__ __forceinline__ float warp_sum(float v) {
    #pragma unroll
    for (int o = 16; o; o >>= 1) v += __shfl_xor_sync(0xffffffffu, v, o);
    return v;
}
__device__ __forceinline__ float warp_max(float v) {
    #pragma unroll
    for (int o = 16; o; o >>= 1) v = fmaxf(v, __shfl_xor_sync(0xffffffffu, v, o));
    return v;
}
__device__ __forceinline__ float gelu_tanh(float x) {
    float x3 = x * x * x;
    return 0.5f * x * (1.0f + tanhf(0.7978845608028654f * (x + 0.044715f * x3)));
}

// ---------------- transpose + fp32 -> bf16 : Wt[n][k] = bf16(W[k][n]) ----------------
__global__ void cvtT_kernel(const float* __restrict__ W, __nv_bfloat16* __restrict__ Wt,
                            int K, int N) {
    __shared__ float t[32][33];
    int n0 = blockIdx.x * 32, k0 = blockIdx.y * 32;
    int tx = threadIdx.x, ty = threadIdx.y;   // (32, 8)
    #pragma unroll
    for (int i = 0; i < 4; i++)
        t[ty + i * 8][tx] = W[(size_t)(k0 + ty + i * 8) * N + n0 + tx];
    __syncthreads();
    #pragma unroll
    for (int i = 0; i < 4; i++)
        Wt[(size_t)(n0 + ty + i * 8) * K + k0 + tx] = __float2bfloat16(t[tx][ty + i * 8]);
}

// ---------------- LayerNorm(x) + no_op head ----------------
__global__ void ln_noop_kernel(const float* __restrict__ x,
                               const float* __restrict__ g, const float* __restrict__ b,
                               const float* __restrict__ nw, const float* __restrict__ nb,
                               __nv_bfloat16* __restrict__ xn, float* __restrict__ out) {
    int row = blockIdx.x, t = threadIdx.x;
    int w = t >> 5, lane = t & 31;
    float4 v = ((const float4*)(x + (size_t)row * C_SZ))[t];

    float s  = v.x + v.y + v.z + v.w;
    float sq = v.x * v.x + v.y * v.y + v.z * v.z + v.w * v.w;

    __shared__ float rs[4], rq[4], rn[4];
    float ws = warp_sum(s), wq = warp_sum(sq);
    if (lane == 0) { rs[w] = ws; rq[w] = wq; }
    __syncthreads();
    float tot_s = rs[0] + rs[1] + rs[2] + rs[3];
    float tot_q = rq[0] + rq[1] + rq[2] + rq[3];
    float mean = tot_s * (1.0f / C_SZ);
    float var  = tot_q * (1.0f / C_SZ) - mean * mean;
    float rstd = rsqrtf(var + 1e-5f);

    float4 gg = ((const float4*)g)[t];
    float4 bb = ((const float4*)b)[t];
    float y0 = (v.x - mean) * rstd * gg.x + bb.x;
    float y1 = (v.y - mean) * rstd * gg.y + bb.y;
    float y2 = (v.z - mean) * rstd * gg.z + bb.z;
    float y3 = (v.w - mean) * rstd * gg.w + bb.w;

    __nv_bfloat162 p0 = __floats2bfloat162_rn(y0, y1);
    __nv_bfloat162 p1 = __floats2bfloat162_rn(y2, y3);
    __nv_bfloat16* xr = xn + (size_t)row * C_SZ + t * 4;
    ((__nv_bfloat162*)xr)[0] = p0;
    ((__nv_bfloat162*)xr)[1] = p1;

    float4 ww = ((const float4*)nw)[t];
    float acc = y0 * ww.x + y1 * ww.y + y2 * ww.z + y3 * ww.w;
    float wacc = warp_sum(acc);
    if (lane == 0) rn[w] = wacc;
    __syncthreads();
    if (t == 0) out[(size_t)row * 65537] = rn[0] + rn[1] + rn[2] + rn[3] + nb[0];
}

// ---------------- mma.sync bf16 GEMM: C[M,N] = act(A[M,K] @ Wt[N,K]^T + bias) ----------------
// CTA tile 128x128, K-chunk 64 (SW128 swizzle), 3-stage cp.async pipeline,
// 8 warps in 4x2 grid, warp tile 32x64, direct register epilogue.
#define GT_THREADS 256
#define GT_STAGE   32768                 // A(16KB) + B(16KB) per stage
#define GT_SMEM    (3 * GT_STAGE + 1024)

template<typename OutT, bool GELU>
__global__ void __launch_bounds__(GT_THREADS)
gemm_mma(const __nv_bfloat16* __restrict__ A, const __nv_bfloat16* __restrict__ Wt,
         const float* __restrict__ bias, OutT* __restrict__ Cout,
         int M, int N, int K) {
    extern __shared__ __align__(16) unsigned char smem_dyn[];
    uint32_t base = (smem_to_u32(smem_dyn) + 1023) & ~1023u;

    int tid = threadIdx.x, warp = tid >> 5, lane = tid & 31;
    int wm = warp >> 1, wn = warp & 1;
    int bm = blockIdx.y, bn = blockIdx.x;
    const int NC = K >> 6;

    // loader: chunk c -> stage c%3 ; 8 x 16B per thread (A then B)
    auto load_chunk = [&](int c) {
        uint32_t sb = base + (c % 3) * GT_STAGE;
        const __nv_bfloat16* Ap = A  + (size_t)bm * 128 * K + (size_t)c * 64;
        const __nv_bfloat16* Bp = Wt + (size_t)bn * 128 * K + (size_t)c * 64;
        #pragma unroll
        for (int i = 0; i < 4; i++) {
            int id = tid + i * 256;            // 0..1023
            int r = id >> 3, j = id & 7;
            uint32_t off = (uint32_t)(r * 128 + j * 16);
            uint32_t sw = off ^ ((off >> 3) & 0x70);
            CP16(sb + sw,         Ap + (size_t)r * K + j * 8);
            CP16(sb + 16384 + sw, Bp + (size_t)r * K + j * 8);
        }
    };

    float acc[2][8][4];
    #pragma unroll
    for (int mi = 0; mi < 2; mi++)
        #pragma unroll
        for (int ni = 0; ni < 8; ni++)
            #pragma unroll
            for (int q = 0; q < 4; q++)
                acc[mi][ni][q] = 0.0f;

    load_chunk(0); CP_COMMIT();
    load_chunk(1); CP_COMMIT();

    // precomputed ldmatrix lane addressing
    int a_row  = wm * 32 + (lane & 15);          // + mi*16
    int a_kc   = (lane >> 4);                    // + ks*2
    int b_row  = wn * 64 + (lane & 7) + ((lane >> 4) & 1) * 8;   // + nj*16
    int b_kc   = (lane >> 3) & 1;                // + ks*2

    for (int c = 0; c < NC; c++) {
        CP_WAIT(1);
        __syncthreads();
        uint32_t sa = base + (c % 3) * GT_STAGE;
        uint32_t sbb = sa + 16384;

        #pragma unroll
        for (int ks = 0; ks < 4; ks++) {
            uint32_t af[2][4];
            #pragma unroll
            for (int mi = 0; mi < 2; mi++) {
                int row = a_row + mi * 16;
                int kc = ks * 2 + a_kc;
                LDSM4(af[mi], sa + row * 128 + ((kc ^ (row & 7)) * 16));
            }
            uint32_t bf[4][4];
            #pragma unroll
            for (int nj = 0; nj < 4; nj++) {
                int row = b_row + nj * 16;
                int kc = ks * 2 + b_kc;
                LDSM4(bf[nj], sbb + row * 128 + ((kc ^ (row & 7)) * 16));
            }
            #pragma unroll
            for (int mi = 0; mi < 2; mi++)
                #pragma unroll
                for (int ni = 0; ni < 8; ni++)
                    mma16816(acc[mi][ni], af[mi], bf[ni >> 1][(ni & 1) * 2],
                             bf[ni >> 1][(ni & 1) * 2 + 1]);
        }
        if (c + 2 < NC) { load_chunk(c + 2); CP_COMMIT(); }
    }

    // epilogue: bias + act, straight from registers
    int erow = bm * 128 + wm * 32 + (lane >> 2);
    int ecol = bn * 128 + wn * 64 + (lane & 3) * 2;
    #pragma unroll
    for (int mi = 0; mi < 2; mi++) {
        #pragma unroll
        for (int ni = 0; ni < 8; ni++) {
            int row = erow + mi * 16;
            int col = ecol + ni * 8;
            float b0 = bias[col], b1 = bias[col + 1];
            float v0 = acc[mi][ni][0] + b0, v1 = acc[mi][ni][1] + b1;
            float v2 = acc[mi][ni][2] + b0, v3 = acc[mi][ni][3] + b1;
            if (GELU) { v0 = gelu_tanh(v0); v1 = gelu_tanh(v1);
                        v2 = gelu_tanh(v2); v3 = gelu_tanh(v3); }
            if (sizeof(OutT) == 2) {
                __nv_bfloat16* op = (__nv_bfloat16*)Cout;
                *(__nv_bfloat162*)(op + (size_t)row * N + col)       = __floats2bfloat162_rn(v0, v1);
                *(__nv_bfloat162*)(op + (size_t)(row + 8) * N + col) = __floats2bfloat162_rn(v2, v3);
            } else {
                float* op = (float*)Cout;
                *(float2*)(op + (size_t)row * N + col)       = make_float2(v0, v1);
                *(float2*)(op + (size_t)(row + 8) * N + col) = make_float2(v2, v3);
            }
        }
    }
}

// ---------------- top-4 per row (one warp per row) ----------------
__global__ void topk_kernel(const float* __restrict__ coarse, int* __restrict__ idx) {
    int warp = threadIdx.x >> 5, lane = threadIdx.x & 31;
    int row = blockIdx.x * 8 + warp;
    const float* cr = coarse + (size_t)row * N_SZ;
    float4 a = ((const float4*)cr)[lane * 2];
    float4 b = ((const float4*)cr)[lane * 2 + 1];
    float v[8] = {a.x, a.y, a.z, a.w, b.x, b.y, b.z, b.w};
    int base = lane * 8;
    #pragma unroll
    for (int k = 0; k < K_TOP; k++) {
        float bv = v[0]; int bi = 0;
        #pragma unroll
        for (int j = 1; j < 8; j++) if (v[j] > bv) { bv = v[j]; bi = j; }
        int bcol = base + bi;
        #pragma unroll
        for (int o = 16; o; o >>= 1) {
            float ov = __shfl_down_sync(0xffffffffu, bv, o);
            int   oc = __shfl_down_sync(0xffffffffu, bcol, o);
            if (ov > bv || (ov == bv && oc < bcol)) { bv = ov; bcol = oc; }
        }
        bcol = __shfl_sync(0xffffffffu, bcol, 0);
        if (lane == 0) idx[row * K_TOP + k] = bcol;
        if (bcol >= base && bcol < base + 8) v[bcol - base] = -INFINITY;
    }
}

// ---------------- gather emb[idx], LN, concat with xn -> fin ----------------
__global__ void embcat_kernel(const int* __restrict__ idx, const float* __restrict__ emb,
                              const float* __restrict__ g, const float* __restrict__ b,
                              const __nv_bfloat16* __restrict__ xn,
                              __nv_bfloat16* __restrict__ fin) {
    int r = blockIdx.x, t = threadIdx.x;         // 128 threads
    int w = t >> 5, lane = t & 31;
    int bq = r >> 2;
    int n = idx[r];

    uint2 xv = ((const uint2*)(xn + (size_t)bq * C_SZ))[t];
    ((uint2*)(fin + (size_t)r * 2 * C_SZ))[t] = xv;

    float4 v = ((const float4*)(emb + (size_t)n * C_SZ))[t];
    float s  = v.x + v.y + v.z + v.w;
    float sq = v.x * v.x + v.y * v.y + v.z * v.z + v.w * v.w;
    __shared__ float rs[4], rq[4];
    float ws = warp_sum(s), wq = warp_sum(sq);
    if (lane == 0) { rs[w] = ws; rq[w] = wq; }
    __syncthreads();
    float tot_s = rs[0] + rs[1] + rs[2] + rs[3];
    float tot_q = rq[0] + rq[1] + rq[2] + rq[3];
    float mean = tot_s * (1.0f / C_SZ);
    float var  = tot_q * (1.0f / C_SZ) - mean * mean;
    float rstd = rsqrtf(var + 1e-5f);

    float4 gg = ((const float4*)g)[t];
    float4 bb = ((const float4*)b)[t];
    float y0 = (v.x - mean) * rstd * gg.x + bb.x;
    float y1 = (v.y - mean) * rstd * gg.y + bb.y;
    float y2 = (v.z - mean) * rstd * gg.z + bb.z;
    float y3 = (v.w - mean) * rstd * gg.w + bb.w;
    __nv_bfloat162 p0 = __floats2bfloat162_rn(y0, y1);
    __nv_bfloat162 p1 = __floats2bfloat162_rn(y2, y3);
    __nv_bfloat16* fr = fin + (size_t)r * 2 * C_SZ + C_SZ + t * 4;
    ((__nv_bfloat162*)fr)[0] = p0;
    ((__nv_bfloat162*)fr)[1] = p1;
}

// ---------------- vals = coarse[b, idx] + log_softmax(fine), in place ----------------
__global__ void vals_kernel(float* __restrict__ fine, const float* __restrict__ coarse,
                            const int* __restrict__ idx) {
    int warp = threadIdx.x >> 5, lane = threadIdx.x & 31;
    int r = blockIdx.x * 8 + warp;
    float4* fr = (float4*)(fine + (size_t)r * F_SZ);
    float4 a = fr[lane * 2], b = fr[lane * 2 + 1];
    float v[8] = {a.x, a.y, a.z, a.w, b.x, b.y, b.z, b.w};
    float m = v[0];
    #pragma unroll
    for (int j = 1; j < 8; j++) m = fmaxf(m, v[j]);
    m = warp_max(m);
    float s = 0.0f;
    #pragma unroll
    for (int j = 0; j < 8; j++) s += expf(v[j] - m);
    s = warp_sum(s);
    float add = coarse[(size_t)(r >> 2) * N_SZ + idx[r]] - m - logf(s);
    a.x = v[0] + add; a.y = v[1] + add; a.z = v[2] + add; a.w = v[3] + add;
    b.x = v[4] + add; b.y = v[5] + add; b.z = v[6] + add; b.w = v[7] + add;
    fr[lane * 2] = a; fr[lane * 2 + 1] = b;
}

// ---------------- permuted broadcast fill of the (B, N*F) output ----------------
__global__ void fill_kernel(const float* __restrict__ coarse, const float* __restrict__ vals,
                            const int* __restrict__ idx, float* __restrict__ out) {
    int ch0 = blockIdx.x, b = blockIdx.y, t = threadIdx.x;   // 256 threads
    __shared__ float base[16];
    __shared__ int ov[16];
    if (t < 16) { base[t] = coarse[(size_t)b * N_SZ + ch0 * 16 + t] - LOG_F; ov[t] = -1; }
    __syncthreads();
    if (t < K_TOP) { int n = idx[b * K_TOP + t]; if ((n >> 4) == ch0) ov[n & 15] = t; }
    __syncthreads();

    size_t obase = (size_t)b * 65537 + 1 + (size_t)ch0 * 4096;
    int head = (int)((4 - (obase & 3)) & 3);
    int nvec = (4096 - head) >> 2;
    int tail = 4096 - head - nvec * 4;

    for (int i = t; i < nvec; i += 256) {
        int p0 = head + i * 4;
        float4 w;
        float* wp = &w.x;
        #pragma unroll
        for (int u = 0; u < 4; u++) {
            int p = p0 + u;
            int ch1 = (p >> 4) & 15;
            int k = ov[ch1];
            wp[u] = (k < 0) ? base[ch1]
                            : vals[((size_t)b * K_TOP + k) * F_SZ + ((p >> 8) << 4) + (p & 15)];
        }
        __stcs((float4*)(out + obase + p0), w);
    }
    int p = -1;
    if (t < head) p = t;
    else if (t - head < tail) p = head + nvec * 4 + (t - head);
    if (p >= 0) {
        int ch1 = (p >> 4) & 15;
        int k = ov[ch1];
        float v = (k < 0) ? base[ch1]
                          : vals[((size_t)b * K_TOP + k) * F_SZ + ((p >> 8) << 4) + (p & 15)];
        out[obase + p] = v;
    }
}

// ---------------- launch ----------------
extern "C" void kernel_launch(void* const* d_in, const int* in_sizes, int n_in,
                              void* d_out, int out_size) {
    const float* x     = (const float*)d_in[0];
    const float* in_g  = (const float*)d_in[1];
    const float* in_b  = (const float*)d_in[2];
    const float* nop_w = (const float*)d_in[3];
    const float* nop_b = (const float*)d_in[4];
    const float* c_w1  = (const float*)d_in[5];
    const float* c_b1  = (const float*)d_in[6];
    const float* c_w2  = (const float*)d_in[7];
    const float* c_b2  = (const float*)d_in[8];
    const float* c_w3  = (const float*)d_in[9];
    const float* c_b3  = (const float*)d_in[10];
    const float* emb   = (const float*)d_in[11];
    const float* emb_g = (const float*)d_in[12];
    const float* emb_b = (const float*)d_in[13];
    const float* f_w1  = (const float*)d_in[14];
    const float* f_b1  = (const float*)d_in[15];
    const float* f_w2  = (const float*)d_in[16];
    const float* f_b2  = (const float*)d_in[17];
    const float* f_w3  = (const float*)d_in[18];
    const float* f_b3  = (const float*)d_in[19];
    float* out = (float*)d_out;

    __nv_bfloat16 *xn, *h1, *h2, *fin, *g1, *g2, *wbf;
    float *coarse, *fine;
    int *idx;
    cudaGetSymbolAddress((void**)&xn,     g_xn);
    cudaGetSymbolAddress((void**)&h1,     g_h1);
    cudaGetSymbolAddress((void**)&h2,     g_h2);
    cudaGetSymbolAddress((void**)&coarse, g_coarse);
    cudaGetSymbolAddress((void**)&idx,    g_topidx);
    cudaGetSymbolAddress((void**)&fin,    g_fin);
    cudaGetSymbolAddress((void**)&g1,     g_g1);
    cudaGetSymbolAddress((void**)&g2,     g_g2);
    cudaGetSymbolAddress((void**)&fine,   g_fine);
    cudaGetSymbolAddress((void**)&wbf,    g_wbf);

    cudaFuncSetAttribute(gemm_mma<__nv_bfloat16, true>,
                         cudaFuncAttributeMaxDynamicSharedMemorySize, GT_SMEM);
    cudaFuncSetAttribute(gemm_mma<float, false>,
                         cudaFuncAttributeMaxDynamicSharedMemorySize, GT_SMEM);

    // weight transpose + fp32 -> bf16 (Wt[n][k] layout = B^T for mma row.col)
    dim3 tb(32, 8);
    cvtT_kernel<<<dim3(512 / 32,  512 / 32),  tb>>>(c_w1, wbf + W_CW1, 512, 512);
    cvtT_kernel<<<dim3(512 / 32,  512 / 32),  tb>>>(c_w2, wbf + W_CW2, 512, 512);
    cvtT_kernel<<<dim3(256 / 32,  512 / 32),  tb>>>(c_w3, wbf + W_CW3, 512, 256);
    cvtT_kernel<<<dim3(512 / 32, 1024 / 32),  tb>>>(f_w1, wbf + W_FW1, 1024, 512);
    cvtT_kernel<<<dim3(512 / 32,  512 / 32),  tb>>>(f_w2, wbf + W_FW2, 512, 512);
    cvtT_kernel<<<dim3(256 / 32,  512 / 32),  tb>>>(f_w3, wbf + W_FW3, 512, 256);

    // LN + no_op head
    ln_noop_kernel<<<B_SZ, 128>>>(x, in_g, in_b, nop_w, nop_b, xn, out);

    // coarse MLP
    gemm_mma<__nv_bfloat16, true ><<<dim3(4, 16), GT_THREADS, GT_SMEM>>>(xn, wbf + W_CW1, c_b1, h1, 2048, 512, 512);
    gemm_mma<__nv_bfloat16, true ><<<dim3(4, 16), GT_THREADS, GT_SMEM>>>(h1, wbf + W_CW2, c_b2, h2, 2048, 512, 512);
    gemm_mma<float,         false><<<dim3(2, 16), GT_THREADS, GT_SMEM>>>(h2, wbf + W_CW3, c_b3, coarse, 2048, 256, 512);

    // top-4 + gather/LN/concat
    topk_kernel<<<B_SZ / 8, 256>>>(coarse, idx);
    embcat_kernel<<<B_SZ * K_TOP, 128>>>(idx, emb, emb_g, emb_b, xn, fin);

    // fine MLP
    gemm_mma<__nv_bfloat16, true ><<<dim3(4, 64), GT_THREADS, GT_SMEM>>>(fin, wbf + W_FW1, f_b1, g1, 8192, 512, 1024);
    gemm_mma<__nv_bfloat16, true ><<<dim3(4, 64), GT_THREADS, GT_SMEM>>>(g1,  wbf + W_FW2, f_b2, g2, 8192, 512, 512);
    gemm_mma<float,         false><<<dim3(2, 64), GT_THREADS, GT_SMEM>>>(g2,  wbf + W_FW3, f_b3, fine, 8192, 256, 512);

    // log-softmax + scatter values, then the big permuted broadcast fill
    vals_kernel<<<B_SZ * K_TOP / 8, 256>>>(fine, coarse, idx);
    fill_kernel<<<dim3(16, B_SZ), 256>>>(coarse, fine, idx, out);
}

// round 4
// speedup vs baseline: 1.4344x; 1.0467x over previous
#include <cuda_runtime.h>
#include <cuda_bf16.h>
#include <math.h>
#include <stdint.h>

#define B_SZ   2048
#define C_SZ   512
#define N_SZ   256
#define F_SZ   256
#define K_TOP  4
#define LOG_F  5.545177444479562f

// ---------------- scratch (static device memory; no allocation) ----------------
__device__ __align__(16) __nv_bfloat16 g_xn  [B_SZ * C_SZ];
__device__ __align__(16) __nv_bfloat16 g_h1  [B_SZ * C_SZ];
__device__ __align__(16) __nv_bfloat16 g_h2  [B_SZ * C_SZ];
__device__ __align__(16) float         g_coarse[B_SZ * N_SZ];
__device__ __align__(16) int           g_topidx[B_SZ * K_TOP];
__device__ __align__(16) float         g_t1  [B_SZ * C_SZ];            // xn @ f_w1[:512]
__device__ __align__(16) __nv_bfloat16 g_e   [B_SZ * K_TOP * C_SZ];    // LN(emb[idx])
__device__ __align__(16) __nv_bfloat16 g_g1  [B_SZ * K_TOP * C_SZ];
__device__ __align__(16) __nv_bfloat16 g_g2  [B_SZ * K_TOP * C_SZ];
__device__ __align__(16) float         g_fine[B_SZ * K_TOP * F_SZ];
__device__ __align__(16) __nv_bfloat16 g_wbf [1572864];   // all weights, [N][K] bf16

// weight offsets in g_wbf
#define W_CW1  0
#define W_CW2  262144
#define W_CW3  524288
#define W_FW1A 655360
#define W_FW1B 917504
#define W_FW2  1179648
#define W_FW3  1441792

// ---------------- PTX helpers ----------------
__device__ __forceinline__ uint32_t smem_to_u32(const void* p) {
    uint32_t a;
    asm("{ .reg .u64 t; cvta.to.shared.u64 t, %1; cvt.u32.u64 %0, t; }" : "=r"(a) : "l"(p));
    return a;
}
#define CP16(dst, src)    asm volatile("cp.async.cg.shared.global [%0], [%1], 16;" :: "r"(dst), "l"(src))
#define CP_COMMIT()       asm volatile("cp.async.commit_group;" ::: "memory")
#define CP_WAIT(n)        asm volatile("cp.async.wait_group %0;" :: "n"(n) : "memory")

#define LDSM4(r, addr)                                                           \
    asm volatile("ldmatrix.sync.aligned.m8n8.x4.shared.b16 {%0,%1,%2,%3}, [%4];" \
        : "=r"((r)[0]), "=r"((r)[1]), "=r"((r)[2]), "=r"((r)[3]) : "r"(addr))

__device__ __forceinline__ void mma16816(float* d, const uint32_t* a,
                                         uint32_t b0, uint32_t b1) {
    asm volatile("mma.sync.aligned.m16n8k16.row.col.f32.bf16.bf16.f32 "
        "{%0,%1,%2,%3}, {%4,%5,%6,%7}, {%8,%9}, {%0,%1,%2,%3};"
        : "+f"(d[0]), "+f"(d[1]), "+f"(d[2]), "+f"(d[3])
        : "r"(a[0]), "r"(a[1]), "r"(a[2]), "r"(a[3]), "r"(b0), "r"(b1));
}

// ---------------- misc helpers ----------------
__device__ __forceinline__ float warp_sum(float v) {
    #pragma unroll
    for (int o = 16; o; o >>= 1) v += __shfl_xor_sync(0xffffffffu, v, o);
    return v;
}
__device__ __forceinline__ float warp_max(float v) {
    #pragma unroll
    for (int o = 16; o; o >>= 1) v = fmaxf(v, __shfl_xor_sync(0xffffffffu, v, o));
    return v;
}
__device__ __forceinline__ float gelu_tanh(float x) {
    float x3 = x * x * x;
    return 0.5f * x * (1.0f + tanhf(0.7978845608028654f * (x + 0.044715f * x3)));
}

// ---------------- merged transpose + fp32 -> bf16 over all weights ----------------
// 7 segments; Wt[n][k] = bf16(W[k][n]); 32x32 tiles, block (32,8)
struct CvtArgs {
    const float*   W[7];
    __nv_bfloat16* Wt[7];
    int K[7], N[7], start[7];
};
__global__ void cvtT_multi(CvtArgs a) {
    __shared__ float t[32][33];
    int seg = 0;
    #pragma unroll
    for (int s = 1; s < 7; s++) if ((int)blockIdx.x >= a.start[s]) seg = s;
    int tile = blockIdx.x - a.start[seg];
    int K = a.K[seg], N = a.N[seg];
    int ntx = N >> 5;
    int n0 = (tile % ntx) * 32, k0 = (tile / ntx) * 32;
    const float* W = a.W[seg];
    __nv_bfloat16* Wt = a.Wt[seg];
    int tx = threadIdx.x, ty = threadIdx.y;
    #pragma unroll
    for (int i = 0; i < 4; i++)
        t[ty + i * 8][tx] = W[(size_t)(k0 + ty + i * 8) * N + n0 + tx];
    __syncthreads();
    #pragma unroll
    for (int i = 0; i < 4; i++)
        Wt[(size_t)(n0 + ty + i * 8) * K + k0 + tx] = __float2bfloat16(t[tx][ty + i * 8]);
}

// ---------------- LayerNorm(x) + no_op head ----------------
__global__ void ln_noop_kernel(const float* __restrict__ x,
                               const float* __restrict__ g, const float* __restrict__ b,
                               const float* __restrict__ nw, const float* __restrict__ nb,
                               __nv_bfloat16* __restrict__ xn, float* __restrict__ out) {
    int row = blockIdx.x, t = threadIdx.x;
    int w = t >> 5, lane = t & 31;
    float4 v = ((const float4*)(x + (size_t)row * C_SZ))[t];

    float s  = v.x + v.y + v.z + v.w;
    float sq = v.x * v.x + v.y * v.y + v.z * v.z + v.w * v.w;

    __shared__ float rs[4], rq[4], rn[4];
    float ws = warp_sum(s), wq = warp_sum(sq);
    if (lane == 0) { rs[w] = ws; rq[w] = wq; }
    __syncthreads();
    float tot_s = rs[0] + rs[1] + rs[2] + rs[3];
    float tot_q = rq[0] + rq[1] + rq[2] + rq[3];
    float mean = tot_s * (1.0f / C_SZ);
    float var  = tot_q * (1.0f / C_SZ) - mean * mean;
    float rstd = rsqrtf(var + 1e-5f);

    float4 gg = ((const float4*)g)[t];
    float4 bb = ((const float4*)b)[t];
    float y0 = (v.x - mean) * rstd * gg.x + bb.x;
    float y1 = (v.y - mean) * rstd * gg.y + bb.y;
    float y2 = (v.z - mean) * rstd * gg.z + bb.z;
    float y3 = (v.w - mean) * rstd * gg.w + bb.w;

    __nv_bfloat162 p0 = __floats2bfloat162_rn(y0, y1);
    __nv_bfloat162 p1 = __floats2bfloat162_rn(y2, y3);
    __nv_bfloat16* xr = xn + (size_t)row * C_SZ + t * 4;
    ((__nv_bfloat162*)xr)[0] = p0;
    ((__nv_bfloat162*)xr)[1] = p1;

    float4 ww = ((const float4*)nw)[t];
    float acc = y0 * ww.x + y1 * ww.y + y2 * ww.z + y3 * ww.w;
    float wacc = warp_sum(acc);
    if (lane == 0) rn[w] = wacc;
    __syncthreads();
    if (t == 0) out[(size_t)row * 65537] = rn[0] + rn[1] + rn[2] + rn[3] + nb[0];
}

// ---------------- mma.sync bf16 GEMM: 64x128 CTA tile, dual-workload launch ----------------
// C[M,N] = act(A[M,K] @ Wt[N,K]^T + bias (+ addrow[row>>2]))
// 8 warps in 2x4 grid, warp tile 32x32, K-chunk 64 (SW128 swizzle), 3-stage cp.async.
#define GT_THREADS 256
#define GT_STAGE   24576                 // A(8KB) + B(16KB) per stage
#define GT_SMEM    (3 * GT_STAGE + 1024)

struct GArgs {
    const __nv_bfloat16* A;
    const __nv_bfloat16* Bw;
    const float* bias;      // nullable
    const float* addrow;    // nullable: += addrow[(row>>2)*N + col]
    __nv_bfloat16* outb;    // one of outb/outf non-null
    float* outf;
    int K, N, gridn, gelu;
};

__global__ void __launch_bounds__(GT_THREADS)
gemm_mma(GArgs a0, GArgs a1, int n0) {
    extern __shared__ __align__(16) unsigned char smem_dyn[];
    uint32_t base = (smem_to_u32(smem_dyn) + 1023) & ~1023u;

    GArgs a = ((int)blockIdx.x < n0) ? a0 : a1;
    int cta = ((int)blockIdx.x < n0) ? blockIdx.x : (blockIdx.x - n0);
    int bm = cta / a.gridn, bn = cta % a.gridn;
    const int K = a.K, N = a.N;
    const int NC = K >> 6;

    int tid = threadIdx.x, warp = tid >> 5, lane = tid & 31;
    int wm = warp >> 2, wn = warp & 3;

    auto load_chunk = [&](int c) {
        uint32_t sb = base + (c % 3) * GT_STAGE;
        const __nv_bfloat16* Ap = a.A  + (size_t)bm * 64 * K + (size_t)c * 64;
        const __nv_bfloat16* Bp = a.Bw + (size_t)bn * 128 * K + (size_t)c * 64;
        #pragma unroll
        for (int i = 0; i < 2; i++) {
            int id = tid + i * 256;
            int r = id >> 3, j = id & 7;
            uint32_t off = (uint32_t)(r * 128 + j * 16);
            uint32_t sw = off ^ ((off >> 3) & 0x70);
            CP16(sb + sw, Ap + (size_t)r * K + j * 8);
        }
        #pragma unroll
        for (int i = 0; i < 4; i++) {
            int id = tid + i * 256;
            int r = id >> 3, j = id & 7;
            uint32_t off = (uint32_t)(r * 128 + j * 16);
            uint32_t sw = off ^ ((off >> 3) & 0x70);
            CP16(sb + 8192 + sw, Bp + (size_t)r * K + j * 8);
        }
    };

    float acc[2][4][4];
    #pragma unroll
    for (int mi = 0; mi < 2; mi++)
        #pragma unroll
        for (int ni = 0; ni < 4; ni++)
            #pragma unroll
            for (int q = 0; q < 4; q++)
                acc[mi][ni][q] = 0.0f;

    load_chunk(0); CP_COMMIT();
    load_chunk(1); CP_COMMIT();

    int a_row = wm * 32 + (lane & 15);
    int a_kc  = (lane >> 4);
    int b_row = wn * 32 + (lane & 7) + ((lane >> 4) & 1) * 8;
    int b_kc  = (lane >> 3) & 1;

    for (int c = 0; c < NC; c++) {
        CP_WAIT(1);
        __syncthreads();
        uint32_t sa = base + (c % 3) * GT_STAGE;
        uint32_t sbb = sa + 8192;

        #pragma unroll
        for (int ks = 0; ks < 4; ks++) {
            uint32_t af[2][4];
            #pragma unroll
            for (int mi = 0; mi < 2; mi++) {
                int row = a_row + mi * 16;
                int kc = ks * 2 + a_kc;
                LDSM4(af[mi], sa + row * 128 + ((kc ^ (row & 7)) * 16));
            }
            uint32_t bf[2][4];
            #pragma unroll
            for (int nj = 0; nj < 2; nj++) {
                int row = b_row + nj * 16;
                int kc = ks * 2 + b_kc;
                LDSM4(bf[nj], sbb + row * 128 + ((kc ^ (row & 7)) * 16));
            }
            #pragma unroll
            for (int mi = 0; mi < 2; mi++)
                #pragma unroll
                for (int ni = 0; ni < 4; ni++)
                    mma16816(acc[mi][ni], af[mi], bf[ni >> 1][(ni & 1) * 2],
                             bf[ni >> 1][(ni & 1) * 2 + 1]);
        }
        if (c + 2 < NC) { load_chunk(c + 2); CP_COMMIT(); }
        __syncthreads();
    }

    // epilogue: bias (+ addrow) + act, straight from registers
    int erow = bm * 64 + wm * 32 + (lane >> 2);
    int ecol = bn * 128 + wn * 32 + (lane & 3) * 2;
    #pragma unroll
    for (int mi = 0; mi < 2; mi++) {
        #pragma unroll
        for (int ni = 0; ni < 4; ni++) {
            int r0 = erow + mi * 16, r1 = r0 + 8;
            int col = ecol + ni * 8;
            float b0 = 0.0f, b1 = 0.0f;
            if (a.bias) { b0 = a.bias[col]; b1 = a.bias[col + 1]; }
            float v0 = acc[mi][ni][0] + b0, v1 = acc[mi][ni][1] + b1;
            float v2 = acc[mi][ni][2] + b0, v3 = acc[mi][ni][3] + b1;
            if (a.addrow) {
                const float* t0 = a.addrow + (size_t)(r0 >> 2) * N + col;
                const float* t1 = a.addrow + (size_t)(r1 >> 2) * N + col;
                v0 += t0[0]; v1 += t0[1]; v2 += t1[0]; v3 += t1[1];
            }
            if (a.gelu) { v0 = gelu_tanh(v0); v1 = gelu_tanh(v1);
                          v2 = gelu_tanh(v2); v3 = gelu_tanh(v3); }
            if (a.outb) {
                *(__nv_bfloat162*)(a.outb + (size_t)r0 * N + col) = __floats2bfloat162_rn(v0, v1);
                *(__nv_bfloat162*)(a.outb + (size_t)r1 * N + col) = __floats2bfloat162_rn(v2, v3);
            } else {
                *(float2*)(a.outf + (size_t)r0 * N + col) = make_float2(v0, v1);
                *(float2*)(a.outf + (size_t)r1 * N + col) = make_float2(v2, v3);
            }
        }
    }
}

// ---------------- top-4 per row (one warp per row) ----------------
__global__ void topk_kernel(const float* __restrict__ coarse, int* __restrict__ idx) {
    int warp = threadIdx.x >> 5, lane = threadIdx.x & 31;
    int row = blockIdx.x * 8 + warp;
    const float* cr = coarse + (size_t)row * N_SZ;
    float4 a = ((const float4*)cr)[lane * 2];
    float4 b = ((const float4*)cr)[lane * 2 + 1];
    float v[8] = {a.x, a.y, a.z, a.w, b.x, b.y, b.z, b.w};
    int base = lane * 8;
    #pragma unroll
    for (int k = 0; k < K_TOP; k++) {
        float bv = v[0]; int bi = 0;
        #pragma unroll
        for (int j = 1; j < 8; j++) if (v[j] > bv) { bv = v[j]; bi = j; }
        int bcol = base + bi;
        #pragma unroll
        for (int o = 16; o; o >>= 1) {
            float ov = __shfl_down_sync(0xffffffffu, bv, o);
            int   oc = __shfl_down_sync(0xffffffffu, bcol, o);
            if (ov > bv || (ov == bv && oc < bcol)) { bv = ov; bcol = oc; }
        }
        bcol = __shfl_sync(0xffffffffu, bcol, 0);
        if (lane == 0) idx[row * K_TOP + k] = bcol;
        if (bcol >= base && bcol < base + 8) v[bcol - base] = -INFINITY;
    }
}

// ---------------- gather emb[idx], LN -> e (bf16) ----------------
__global__ void embcat_kernel(const int* __restrict__ idx, const float* __restrict__ emb,
                              const float* __restrict__ g, const float* __restrict__ b,
                              __nv_bfloat16* __restrict__ e) {
    int r = blockIdx.x, t = threadIdx.x;         // 128 threads
    int w = t >> 5, lane = t & 31;
    int n = idx[r];

    float4 v = ((const float4*)(emb + (size_t)n * C_SZ))[t];
    float s  = v.x + v.y + v.z + v.w;
    float sq = v.x * v.x + v.y * v.y + v.z * v.z + v.w * v.w;
    __shared__ float rs[4], rq[4];
    float ws = warp_sum(s), wq = warp_sum(sq);
    if (lane == 0) { rs[w] = ws; rq[w] = wq; }
    __syncthreads();
    float tot_s = rs[0] + rs[1] + rs[2] + rs[3];
    float tot_q = rq[0] + rq[1] + rq[2] + rq[3];
    float mean = tot_s * (1.0f / C_SZ);
    float var  = tot_q * (1.0f / C_SZ) - mean * mean;
    float rstd = rsqrtf(var + 1e-5f);

    float4 gg = ((const float4*)g)[t];
    float4 bb = ((const float4*)b)[t];
    float y0 = (v.x - mean) * rstd * gg.x + bb.x;
    float y1 = (v.y - mean) * rstd * gg.y + bb.y;
    float y2 = (v.z - mean) * rstd * gg.z + bb.z;
    float y3 = (v.w - mean) * rstd * gg.w + bb.w;
    __nv_bfloat16* fr = e + (size_t)r * C_SZ + t * 4;
    ((__nv_bfloat162*)fr)[0] = __floats2bfloat162_rn(y0, y1);
    ((__nv_bfloat162*)fr)[1] = __floats2bfloat162_rn(y2, y3);
}

// ---------------- vals = coarse[b, idx] + log_softmax(fine), in place ----------------
__global__ void vals_kernel(float* __restrict__ fine, const float* __restrict__ coarse,
                            const int* __restrict__ idx) {
    int warp = threadIdx.x >> 5, lane = threadIdx.x & 31;
    int r = blockIdx.x * 8 + warp;
    float4* fr = (float4*)(fine + (size_t)r * F_SZ);
    float4 a = fr[lane * 2], b = fr[lane * 2 + 1];
    float v[8] = {a.x, a.y, a.z, a.w, b.x, b.y, b.z, b.w};
    float m = v[0];
    #pragma unroll
    for (int j = 1; j < 8; j++) m = fmaxf(m, v[j]);
    m = warp_max(m);
    float s = 0.0f;
    #pragma unroll
    for (int j = 0; j < 8; j++) s += expf(v[j] - m);
    s = warp_sum(s);
    float add = coarse[(size_t)(r >> 2) * N_SZ + idx[r]] - m - logf(s);
    a.x = v[0] + add; a.y = v[1] + add; a.z = v[2] + add; a.w = v[3] + add;
    b.x = v[4] + add; b.y = v[5] + add; b.z = v[6] + add; b.w = v[7] + add;
    fr[lane * 2] = a; fr[lane * 2 + 1] = b;
}

// ---------------- permuted broadcast fill of the (B, N*F) output ----------------
__global__ void fill_kernel(const float* __restrict__ coarse, const float* __restrict__ vals,
                            const int* __restrict__ idx, float* __restrict__ out) {
    int ch0 = blockIdx.x, b = blockIdx.y, t = threadIdx.x;   // 256 threads
    __shared__ float base[16];
    __shared__ int ov[16];
    if (t < 16) { base[t] = coarse[(size_t)b * N_SZ + ch0 * 16 + t] - LOG_F; ov[t] = -1; }
    __syncthreads();
    if (t < K_TOP) { int n = idx[b * K_TOP + t]; if ((n >> 4) == ch0) ov[n & 15] = t; }
    __syncthreads();

    size_t obase = (size_t)b * 65537 + 1 + (size_t)ch0 * 4096;
    int head = (int)((4 - (obase & 3)) & 3);
    int nvec = (4096 - head) >> 2;
    int tail = 4096 - head - nvec * 4;

    for (int i = t; i < nvec; i += 256) {
        int p0 = head + i * 4;
        float4 w;
        float* wp = &w.x;
        #pragma unroll
        for (int u = 0; u < 4; u++) {
            int p = p0 + u;
            int ch1 = (p >> 4) & 15;
            int k = ov[ch1];
            wp[u] = (k < 0) ? base[ch1]
                            : vals[((size_t)b * K_TOP + k) * F_SZ + ((p >> 8) << 4) + (p & 15)];
        }
        __stcs((float4*)(out + obase + p0), w);
    }
    int p = -1;
    if (t < head) p = t;
    else if (t - head < tail) p = head + nvec * 4 + (t - head);
    if (p >= 0) {
        int ch1 = (p >> 4) & 15;
        int k = ov[ch1];
        float v = (k < 0) ? base[ch1]
                          : vals[((size_t)b * K_TOP + k) * F_SZ + ((p >> 8) << 4) + (p & 15)];
        out[obase + p] = v;
    }
}

// ---------------- launch ----------------
extern "C" void kernel_launch(void* const* d_in, const int* in_sizes, int n_in,
                              void* d_out, int out_size) {
    const float* x     = (const float*)d_in[0];
    const float* in_g  = (const float*)d_in[1];
    const float* in_b  = (const float*)d_in[2];
    const float* nop_w = (const float*)d_in[3];
    const float* nop_b = (const float*)d_in[4];
    const float* c_w1  = (const float*)d_in[5];
    const float* c_b1  = (const float*)d_in[6];
    const float* c_w2  = (const float*)d_in[7];
    const float* c_b2  = (const float*)d_in[8];
    const float* c_w3  = (const float*)d_in[9];
    const float* c_b3  = (const float*)d_in[10];
    const float* emb   = (const float*)d_in[11];
    const float* emb_g = (const float*)d_in[12];
    const float* emb_b = (const float*)d_in[13];
    const float* f_w1  = (const float*)d_in[14];
    const float* f_b1  = (const float*)d_in[15];
    const float* f_w2  = (const float*)d_in[16];
    const float* f_b2  = (const float*)d_in[17];
    const float* f_w3  = (const float*)d_in[18];
    const float* f_b3  = (const float*)d_in[19];
    float* out = (float*)d_out;

    __nv_bfloat16 *xn, *h1, *h2, *e, *g1, *g2, *wbf;
    float *coarse, *fine, *t1;
    int *idx;
    cudaGetSymbolAddress((void**)&xn,     g_xn);
    cudaGetSymbolAddress((void**)&h1,     g_h1);
    cudaGetSymbolAddress((void**)&h2,     g_h2);
    cudaGetSymbolAddress((void**)&coarse, g_coarse);
    cudaGetSymbolAddress((void**)&idx,    g_topidx);
    cudaGetSymbolAddress((void**)&t1,     g_t1);
    cudaGetSymbolAddress((void**)&e,      g_e);
    cudaGetSymbolAddress((void**)&g1,     g_g1);
    cudaGetSymbolAddress((void**)&g2,     g_g2);
    cudaGetSymbolAddress((void**)&fine,   g_fine);
    cudaGetSymbolAddress((void**)&wbf,    g_wbf);

    cudaFuncSetAttribute(gemm_mma, cudaFuncAttributeMaxDynamicSharedMemorySize, GT_SMEM);

    // merged weight transpose+convert (7 segments, 1536 tiles of 32x32)
    {
        CvtArgs ca;
        const float*   srcs[7] = {c_w1, c_w2, c_w3, f_w1, f_w1 + 512 * 512, f_w2, f_w3};
        __nv_bfloat16* dsts[7] = {wbf + W_CW1, wbf + W_CW2, wbf + W_CW3, wbf + W_FW1A,
                                  wbf + W_FW1B, wbf + W_FW2, wbf + W_FW3};
        int Ks[7] = {512, 512, 512, 512, 512, 512, 512};
        int Ns[7] = {512, 512, 256, 512, 512, 512, 256};
        int st = 0;
        for (int s = 0; s < 7; s++) {
            ca.W[s] = srcs[s]; ca.Wt[s] = dsts[s]; ca.K[s] = Ks[s]; ca.N[s] = Ns[s];
            ca.start[s] = st;
            st += (Ks[s] >> 5) * (Ns[s] >> 5);
        }
        cvtT_multi<<<st, dim3(32, 8)>>>(ca);
    }

    // LN + no_op head
    ln_noop_kernel<<<B_SZ, 128>>>(x, in_g, in_b, nop_w, nop_b, xn, out);

    GArgs Z = {};
    // pair launch: coarse GEMM1 (128 CTAs) + t1 = xn @ f_w1a (128 CTAs)
    {
        GArgs a0 = Z, a1 = Z;
        a0.A = xn; a0.Bw = wbf + W_CW1; a0.bias = c_b1; a0.outb = h1;
        a0.K = 512; a0.N = 512; a0.gridn = 4; a0.gelu = 1;
        a1.A = xn; a1.Bw = wbf + W_FW1A; a1.outf = t1;
        a1.K = 512; a1.N = 512; a1.gridn = 4; a1.gelu = 0;
        gemm_mma<<<256, GT_THREADS, GT_SMEM>>>(a0, a1, 128);
    }
    // coarse GEMM2
    {
        GArgs a = Z;
        a.A = h1; a.Bw = wbf + W_CW2; a.bias = c_b2; a.outb = h2;
        a.K = 512; a.N = 512; a.gridn = 4; a.gelu = 1;
        gemm_mma<<<128, GT_THREADS, GT_SMEM>>>(a, a, 128);
    }
    // coarse GEMM3 -> coarse (fp32)
    {
        GArgs a = Z;
        a.A = h2; a.Bw = wbf + W_CW3; a.bias = c_b3; a.outf = coarse;
        a.K = 512; a.N = 256; a.gridn = 2; a.gelu = 0;
        gemm_mma<<<64, GT_THREADS, GT_SMEM>>>(a, a, 64);
    }

    // top-4 + gather/LN
    topk_kernel<<<B_SZ / 8, 256>>>(coarse, idx);
    embcat_kernel<<<B_SZ * K_TOP, 128>>>(idx, emb, emb_g, emb_b, e);

    // fine GEMM1 (e-part only, adds t1[row>>2] + bias, gelu)
    {
        GArgs a = Z;
        a.A = e; a.Bw = wbf + W_FW1B; a.bias = f_b1; a.addrow = t1; a.outb = g1;
        a.K = 512; a.N = 512; a.gridn = 4; a.gelu = 1;
        gemm_mma<<<512, GT_THREADS, GT_SMEM>>>(a, a, 512);
    }
    // fine GEMM2
    {
        GArgs a = Z;
        a.A = g1; a.Bw = wbf + W_FW2; a.bias = f_b2; a.outb = g2;
        a.K = 512; a.N = 512; a.gridn = 4; a.gelu = 1;
        gemm_mma<<<512, GT_THREADS, GT_SMEM>>>(a, a, 512);
    }
    // fine GEMM3 -> fine (fp32)
    {
        GArgs a = Z;
        a.A = g2; a.Bw = wbf + W_FW3; a.bias = f_b3; a.outf = fine;
        a.K = 512; a.N = 256; a.gridn = 2; a.gelu = 0;
        gemm_mma<<<256, GT_THREADS, GT_SMEM>>>(a, a, 256);
    }

    // log-softmax + scatter values, then the big permuted broadcast fill
    vals_kernel<<<B_SZ * K_TOP / 8, 256>>>(fine, coarse, idx);
    fill_kernel<<<dim3(16, B_SZ), 256>>>(coarse, fine, idx, out);
}